// round 6
// baseline (speedup 1.0000x reference)
#include <cuda_runtime.h>
#include <cuda_bf16.h>

typedef unsigned long long u64;

// ===========================================================================
// Compile-time CG machinery (all constexpr, double precision)
// ===========================================================================
__host__ __device__ constexpr double cfct(int k) {
    double r = 1.0;
    for (int i = 2; i <= k; ++i) r *= (double)i;
    return r;
}
__host__ __device__ constexpr double csqrt(double x) {
    if (x <= 0.0) return 0.0;
    double g = x < 1.0 ? 1.0 : x;
    for (int i = 0; i < 40; ++i) g = 0.5 * (g + x / g);
    return g;
}
__host__ __device__ constexpr double csu2(int j1,int m1,int j2,int m2,int j3,int m3) {
    if (m1 + m2 != m3) return 0.0;
    if (m3 > j3 || m3 < -j3) return 0.0;
    int vmin = -j1 + j2 + m3; if (-j1 + m1 > vmin) vmin = -j1 + m1; if (vmin < 0) vmin = 0;
    int vmax = j2 + j3 + m1; if (j3 - j1 + j2 < vmax) vmax = j3 - j1 + j2; if (j3 + m3 < vmax) vmax = j3 + m3;
    if (vmax < vmin) return 0.0;
    double C = (2.0*j3 + 1.0)
             * (cfct(j3+j1-j2)*cfct(j3-j1+j2)*cfct(j1+j2-j3)*cfct(j3+m3)*cfct(j3-m3))
             / (cfct(j1+j2+j3+1)*cfct(j1-m1)*cfct(j1+m1)*cfct(j2-m2)*cfct(j2+m2));
    double S = 0.0;
    for (int v = vmin; v <= vmax; ++v) {
        double t = (cfct(j2+j3+m1-v)*cfct(j1-m1+v))
                 / (cfct(v)*cfct(j3-j1+j2-v)*cfct(j3+m3-v)*cfct(v+j1-j2-m3));
        S += (((v + j2 + m2) & 1) ? -t : t);
    }
    return csqrt(C) * S;
}

struct cc { double r, i; };
__host__ __device__ constexpr cc cmulc(cc a, cc b) {
    return cc{a.r*b.r - a.i*b.i, a.r*b.i + a.i*b.r};
}
__host__ __device__ constexpr cc qent(int l, int mu, int m) {
    const double invs = 0.70710678118654752440;
    cc q{0.0, 0.0};
    if (mu == 0) {
        if (m != 0) return cc{0.0, 0.0};
        q = cc{1.0, 0.0};
    } else if (mu < 0) {
        if (m == -mu)      q = cc{invs, 0.0};
        else if (m == mu)  q = cc{0.0, -invs};
        else return cc{0.0, 0.0};
    } else {
        if (m == mu)       q = cc{(mu & 1) ? -invs : invs, 0.0};
        else if (m == -mu) q = cc{0.0, (mu & 1) ? -invs : invs};
        else return cc{0.0, 0.0};
    }
    cc o{0.0, 0.0};
    switch (l & 3) {
        case 0: o = q; break;
        case 1: o = cc{ q.i, -q.r}; break;
        case 2: o = cc{-q.r, -q.i}; break;
        default: o = cc{-q.i,  q.r}; break;
    }
    return o;
}
__host__ __device__ constexpr double ccgreal(int l1,int m1,int l2,int m2,int l3,int m3) {
    double acc = 0.0;
    int am1 = m1 < 0 ? -m1 : m1;
    int am2 = m2 < 0 ? -m2 : m2;
    for (int s1 = 0; s1 < 2; ++s1) {
        if (am1 == 0 && s1 == 1) continue;
        int mu1 = s1 ? -am1 : am1;
        cc q1 = qent(l1, mu1, m1);
        for (int s2 = 0; s2 < 2; ++s2) {
            if (am2 == 0 && s2 == 1) continue;
            int mu2 = s2 ? -am2 : am2;
            int mu3 = mu1 + mu2;
            if (mu3 > l3 || mu3 < -l3) continue;
            cc q3 = qent(l3, mu3, m3);
            if (q3.r == 0.0 && q3.i == 0.0) continue;
            q3.i = -q3.i;
            double cg = csu2(l1, mu1, l2, mu2, l3, mu3);
            if (cg == 0.0) continue;
            cc t = cmulc(cmulc(q1, qent(l2, mu2, m2)), q3);
            acc += t.r * cg;
        }
    }
    return acc;
}

__host__ __device__ constexpr int pathof(int lo, int l1, int l2) {
    const signed char L[64] = {
       0,-1,-1,-1, -1, 1,-1,-1, -1,-1, 2,-1, -1,-1,-1, 3,
      -1, 4,-1,-1,  5,-1, 6,-1, -1, 7,-1, 8, -1,-1, 9,-1,
      -1,-1,10,-1, -1,11,-1,12, 13,-1,14,-1, -1,15,-1,16,
      -1,-1,-1,17, -1,-1,18,-1, -1,19,-1,20, 21,-1,22,-1
    };
    return L[lo*16 + l1*4 + l2];
}

__host__ __device__ constexpr bool term_ok(int l1,int m1,int l2,int m2,int lo,int m3) {
    if ((l1 + l2 + lo) & 1) return false;
    int dl = l1 - l2; if (dl < 0) dl = -dl;
    if (lo < dl || lo > l1 + l2) return false;
    int am1 = m1 < 0 ? -m1 : m1;
    int am2 = m2 < 0 ? -m2 : m2;
    int am3 = m3 < 0 ? -m3 : m3;
    int s = am1 + am2;
    int d = am1 - am2; if (d < 0) d = -d;
    if (am3 != s && am3 != d) return false;
    if ((((m1 < 0) ? 1 : 0) + ((m2 < 0) ? 1 : 0) + ((m3 < 0) ? 1 : 0)) & 1) return false;
    return true;
}

struct CGT { float v[4096]; };
__host__ __device__ constexpr CGT make_cgt() {
    CGT t{};
    for (int a = 0; a < 16; ++a)
    for (int b = 0; b < 16; ++b)
    for (int c = 0; c < 16; ++c) {
        int l1 = (a >= 9) ? 3 : (a >= 4) ? 2 : (a >= 1) ? 1 : 0;
        int l2 = (b >= 9) ? 3 : (b >= 4) ? 2 : (b >= 1) ? 1 : 0;
        int lo = (c >= 9) ? 3 : (c >= 4) ? 2 : (c >= 1) ? 1 : 0;
        int m1 = a - l1*l1 - l1;
        int m2 = b - l2*l2 - l2;
        int m3 = c - lo*lo - lo;
        double val = 0.0;
        if (pathof(lo, l1, l2) >= 0 && term_ok(l1, m1, l2, m2, lo, m3))
            val = csqrt(2.0*lo + 1.0) * ccgreal(l1, m1, l2, m2, lo, m3);
        t.v[(a*16 + b)*16 + c] = (float)val;
    }
    return t;
}

// ===========================================================================
// Packed f32x2 helpers
// ===========================================================================
__device__ __forceinline__ u64 pk2(float lo, float hi) {
    u64 r; asm("mov.b64 %0, {%1, %2};" : "=l"(r) : "f"(lo), "f"(hi)); return r;
}
__device__ __forceinline__ void upk2(float& lo, float& hi, u64 v) {
    asm("mov.b64 {%0, %1}, %2;" : "=f"(lo), "=f"(hi) : "l"(v));
}
__device__ __forceinline__ u64 mul2(u64 a, u64 b) {
    u64 r; asm("mul.rn.f32x2 %0, %1, %2;" : "=l"(r) : "l"(a), "l"(b)); return r;
}
__device__ __forceinline__ u64 fma2(u64 a, u64 b, u64 c) {
    u64 r; asm("fma.rn.f32x2 %0, %1, %2, %3;" : "=l"(r) : "l"(a), "l"(b), "l"(c)); return r;
}

__device__ __forceinline__ void load_row(const float* __restrict__ p, int r, int n, float v[16]) {
    if (r < n) {
        const float4* q = (const float4*)p + r * 4;
        #pragma unroll
        for (int i = 0; i < 4; ++i) {
            float4 t = q[i];
            v[4*i] = t.x; v[4*i+1] = t.y; v[4*i+2] = t.z; v[4*i+3] = t.w;
        }
    } else {
        #pragma unroll
        for (int i = 0; i < 16; ++i) v[i] = 0.f;
    }
}

__device__ __forceinline__ void store_row(float* __restrict__ out, int r, int n, const float v[16]) {
    if (r < n) {
        float4* q = (float4*)out + r * 4;
        #pragma unroll
        for (int i = 0; i < 4; ++i)
            q[i] = make_float4(v[4*i], v[4*i+1], v[4*i+2], v[4*i+3]);
    }
}

// ===========================================================================
// Main kernel: 4 rows/thread as two f32x2 chains sharing cg constant regs.
// ===========================================================================
__global__ void __launch_bounds__(128, 2)
tp_main(const float* __restrict__ x1, const float* __restrict__ x2,
        const float* __restrict__ weights, float* __restrict__ out, int n) {
    static constexpr CGT CG = make_cgt();

    const int r0 = blockIdx.x * 512 + threadIdx.x;
    const int r1 = r0 + 128, r2 = r0 + 256, r3 = r0 + 384;

    // Chain A = rows (r0, r1); chain B = rows (r2, r3)
    u64 X1A[16], X1B[16], X2A[16], X2B[16], AC0[16], AC1[16];
    {
        float t0[16], t1[16];
        load_row(x1, r0, n, t0); load_row(x1, r1, n, t1);
        #pragma unroll
        for (int i = 0; i < 16; ++i) X1A[i] = pk2(t0[i], t1[i]);
        load_row(x1, r2, n, t0); load_row(x1, r3, n, t1);
        #pragma unroll
        for (int i = 0; i < 16; ++i) X1B[i] = pk2(t0[i], t1[i]);
        load_row(x2, r0, n, t0); load_row(x2, r1, n, t1);
        #pragma unroll
        for (int i = 0; i < 16; ++i) X2A[i] = pk2(t0[i], t1[i]);
        load_row(x2, r2, n, t0); load_row(x2, r3, n, t1);
        #pragma unroll
        for (int i = 0; i < 16; ++i) X2B[i] = pk2(t0[i], t1[i]);
    }

    bool acI[16];                 // first-write flags (fold after unroll)
    #pragma unroll
    for (int i = 0; i < 16; ++i) acI[i] = false;

    // (l1,l2)-block loop. Each block has at most two output l's: loX, loY.
    #pragma unroll
    for (int l1 = 0; l1 <= 3; ++l1)
    #pragma unroll
    for (int l2 = 0; l2 <= 3; ++l2) {
        const int dl  = l1 > l2 ? l1 - l2 : l2 - l1;
        const int loX = dl;                                   // parity-valid
        const int hi  = (l1 + l2 < 3) ? (l1 + l2) : 3;
        const int loY = (dl + 2 <= hi) ? dl + 2 : -1;

        u64 tX0[7], tX1[7], tY0[7], tY1[7];
        bool fX[7], fY[7];
        #pragma unroll
        for (int i = 0; i < 7; ++i) { fX[i] = false; fY[i] = false; }

        #pragma unroll
        for (int m1 = -3; m1 <= 3; ++m1) {
            if (m1 < -l1 || m1 > l1) continue;
            #pragma unroll
            for (int m2 = -3; m2 <= 3; ++m2) {
                if (m2 < -l2 || m2 > l2) continue;
                const int a = l1*l1 + l1 + m1;
                const int b = l2*l2 + l2 + m2;
                const u64 pa0 = mul2(X1A[a], X2A[b]);
                const u64 pa1 = mul2(X1B[a], X2B[b]);
                #pragma unroll
                for (int s = 0; s < 2; ++s) {
                    const int lo = (s == 0) ? loX : loY;
                    if (lo < 0) continue;
                    #pragma unroll
                    for (int m3 = -3; m3 <= 3; ++m3) {
                        if (m3 < -lo || m3 > lo) continue;
                        if (!term_ok(l1, m1, l2, m2, lo, m3)) continue;
                        const int c = lo*lo + lo + m3;
                        const float cg = CG.v[(a*16 + b)*16 + c];  // imm
                        if (cg == 0.f) continue;
                        const u64 w = pk2(cg, cg);                 // shared
                        const int k = lo + m3;
                        if (s == 0) {
                            if (!fX[k]) { tX0[k] = mul2(w, pa0); tX1[k] = mul2(w, pa1); fX[k] = true; }
                            else        { tX0[k] = fma2(w, pa0, tX0[k]); tX1[k] = fma2(w, pa1, tX1[k]); }
                        } else {
                            if (!fY[k]) { tY0[k] = mul2(w, pa0); tY1[k] = mul2(w, pa1); fY[k] = true; }
                            else        { tY0[k] = fma2(w, pa0, tY0[k]); tY1[k] = fma2(w, pa1, tY1[k]); }
                        }
                    }
                }
            }
        }

        // Finalize: AC[c] += w_path * t[...]
        #pragma unroll
        for (int s = 0; s < 2; ++s) {
            const int lo = (s == 0) ? loX : loY;
            if (lo < 0) continue;
            const int p = pathof(lo, l1, l2);
            const float wp = __ldg(weights + p);
            const u64 w2 = pk2(wp, wp);
            #pragma unroll
            for (int m3 = -3; m3 <= 3; ++m3) {
                if (m3 < -lo || m3 > lo) continue;
                const int k = lo + m3;
                const bool have = (s == 0) ? fX[k] : fY[k];
                if (!have) continue;
                const u64 t0v = (s == 0) ? tX0[k] : tY0[k];
                const u64 t1v = (s == 0) ? tX1[k] : tY1[k];
                const int c = lo*lo + lo + m3;
                if (!acI[c]) {
                    AC0[c] = mul2(w2, t0v);
                    AC1[c] = mul2(w2, t1v);
                    acI[c] = true;
                } else {
                    AC0[c] = fma2(w2, t0v, AC0[c]);
                    AC1[c] = fma2(w2, t1v, AC1[c]);
                }
            }
        }
    }

    // Every c in 0..15 is written by at least one path (verified: lo=0..3 all
    // have paths), so acI[c] is true for all c here.
    float o0[16], o1[16], o2[16], o3[16];
    #pragma unroll
    for (int i = 0; i < 16; ++i) { upk2(o0[i], o1[i], AC0[i]); upk2(o2[i], o3[i], AC1[i]); }
    store_row(out, r0, n, o0);
    store_row(out, r1, n, o1);
    store_row(out, r2, n, o2);
    store_row(out, r3, n, o3);
}

extern "C" void kernel_launch(void* const* d_in, const int* in_sizes, int n_in,
                              void* d_out, int out_size) {
    const float* x1 = (const float*)d_in[0];
    const float* x2 = (const float*)d_in[1];
    const float* weights = (const float*)d_in[2];
    float* out = (float*)d_out;
    const int n = in_sizes[0] / 16;

    const int blocks = (n + 511) / 512;
    tp_main<<<blocks, 128>>>(x1, x2, weights, out, n);
}

// round 7
// speedup vs baseline: 10.9814x; 10.9814x over previous
#include <cuda_runtime.h>
#include <cuda_bf16.h>

typedef unsigned long long u64;

// ===========================================================================
// Compile-time CG machinery (all constexpr, double precision)
// ===========================================================================
__host__ __device__ constexpr double cfct(int k) {
    double r = 1.0;
    for (int i = 2; i <= k; ++i) r *= (double)i;
    return r;
}
__host__ __device__ constexpr double csqrt(double x) {
    if (x <= 0.0) return 0.0;
    double g = x < 1.0 ? 1.0 : x;
    for (int i = 0; i < 40; ++i) g = 0.5 * (g + x / g);
    return g;
}
__host__ __device__ constexpr double csu2(int j1,int m1,int j2,int m2,int j3,int m3) {
    if (m1 + m2 != m3) return 0.0;
    if (m3 > j3 || m3 < -j3) return 0.0;
    int vmin = -j1 + j2 + m3; if (-j1 + m1 > vmin) vmin = -j1 + m1; if (vmin < 0) vmin = 0;
    int vmax = j2 + j3 + m1; if (j3 - j1 + j2 < vmax) vmax = j3 - j1 + j2; if (j3 + m3 < vmax) vmax = j3 + m3;
    if (vmax < vmin) return 0.0;
    double C = (2.0*j3 + 1.0)
             * (cfct(j3+j1-j2)*cfct(j3-j1+j2)*cfct(j1+j2-j3)*cfct(j3+m3)*cfct(j3-m3))
             / (cfct(j1+j2+j3+1)*cfct(j1-m1)*cfct(j1+m1)*cfct(j2-m2)*cfct(j2+m2));
    double S = 0.0;
    for (int v = vmin; v <= vmax; ++v) {
        double t = (cfct(j2+j3+m1-v)*cfct(j1-m1+v))
                 / (cfct(v)*cfct(j3-j1+j2-v)*cfct(j3+m3-v)*cfct(v+j1-j2-m3));
        S += (((v + j2 + m2) & 1) ? -t : t);
    }
    return csqrt(C) * S;
}

struct cc { double r, i; };
__host__ __device__ constexpr cc cmulc(cc a, cc b) {
    return cc{a.r*b.r - a.i*b.i, a.r*b.i + a.i*b.r};
}
__host__ __device__ constexpr cc qent(int l, int mu, int m) {
    const double invs = 0.70710678118654752440;
    cc q{0.0, 0.0};
    if (mu == 0) {
        if (m != 0) return cc{0.0, 0.0};
        q = cc{1.0, 0.0};
    } else if (mu < 0) {
        if (m == -mu)      q = cc{invs, 0.0};
        else if (m == mu)  q = cc{0.0, -invs};
        else return cc{0.0, 0.0};
    } else {
        if (m == mu)       q = cc{(mu & 1) ? -invs : invs, 0.0};
        else if (m == -mu) q = cc{0.0, (mu & 1) ? -invs : invs};
        else return cc{0.0, 0.0};
    }
    cc o{0.0, 0.0};
    switch (l & 3) {
        case 0: o = q; break;
        case 1: o = cc{ q.i, -q.r}; break;
        case 2: o = cc{-q.r, -q.i}; break;
        default: o = cc{-q.i,  q.r}; break;
    }
    return o;
}
__host__ __device__ constexpr double ccgreal(int l1,int m1,int l2,int m2,int l3,int m3) {
    double acc = 0.0;
    int am1 = m1 < 0 ? -m1 : m1;
    int am2 = m2 < 0 ? -m2 : m2;
    for (int s1 = 0; s1 < 2; ++s1) {
        if (am1 == 0 && s1 == 1) continue;
        int mu1 = s1 ? -am1 : am1;
        cc q1 = qent(l1, mu1, m1);
        for (int s2 = 0; s2 < 2; ++s2) {
            if (am2 == 0 && s2 == 1) continue;
            int mu2 = s2 ? -am2 : am2;
            int mu3 = mu1 + mu2;
            if (mu3 > l3 || mu3 < -l3) continue;
            cc q3 = qent(l3, mu3, m3);
            if (q3.r == 0.0 && q3.i == 0.0) continue;
            q3.i = -q3.i;
            double cg = csu2(l1, mu1, l2, mu2, l3, mu3);
            if (cg == 0.0) continue;
            cc t = cmulc(cmulc(q1, qent(l2, mu2, m2)), q3);
            acc += t.r * cg;
        }
    }
    return acc;
}

__host__ __device__ constexpr int pathof(int lo, int l1, int l2) {
    const signed char L[64] = {
       0,-1,-1,-1, -1, 1,-1,-1, -1,-1, 2,-1, -1,-1,-1, 3,
      -1, 4,-1,-1,  5,-1, 6,-1, -1, 7,-1, 8, -1,-1, 9,-1,
      -1,-1,10,-1, -1,11,-1,12, 13,-1,14,-1, -1,15,-1,16,
      -1,-1,-1,17, -1,-1,18,-1, -1,19,-1,20, 21,-1,22,-1
    };
    return L[lo*16 + l1*4 + l2];
}

__host__ __device__ constexpr bool term_ok(int l1,int m1,int l2,int m2,int lo,int m3) {
    if ((l1 + l2 + lo) & 1) return false;
    int dl = l1 - l2; if (dl < 0) dl = -dl;
    if (lo < dl || lo > l1 + l2) return false;
    int am1 = m1 < 0 ? -m1 : m1;
    int am2 = m2 < 0 ? -m2 : m2;
    int am3 = m3 < 0 ? -m3 : m3;
    int s = am1 + am2;
    int d = am1 - am2; if (d < 0) d = -d;
    if (am3 != s && am3 != d) return false;
    if ((((m1 < 0) ? 1 : 0) + ((m2 < 0) ? 1 : 0) + ((m3 < 0) ? 1 : 0)) & 1) return false;
    return true;
}

struct CGT { float v[4096]; };
__host__ __device__ constexpr CGT make_cgt() {
    CGT t{};
    for (int a = 0; a < 16; ++a)
    for (int b = 0; b < 16; ++b)
    for (int c = 0; c < 16; ++c) {
        int l1 = (a >= 9) ? 3 : (a >= 4) ? 2 : (a >= 1) ? 1 : 0;
        int l2 = (b >= 9) ? 3 : (b >= 4) ? 2 : (b >= 1) ? 1 : 0;
        int lo = (c >= 9) ? 3 : (c >= 4) ? 2 : (c >= 1) ? 1 : 0;
        int m1 = a - l1*l1 - l1;
        int m2 = b - l2*l2 - l2;
        int m3 = c - lo*lo - lo;
        double val = 0.0;
        if (pathof(lo, l1, l2) >= 0 && term_ok(l1, m1, l2, m2, lo, m3))
            val = csqrt(2.0*lo + 1.0) * ccgreal(l1, m1, l2, m2, lo, m3);
        t.v[(a*16 + b)*16 + c] = (float)val;
    }
    return t;
}

// ===========================================================================
// Packed f32x2 helpers
// ===========================================================================
__device__ __forceinline__ u64 pk2(float lo, float hi) {
    u64 r; asm("mov.b64 %0, {%1, %2};" : "=l"(r) : "f"(lo), "f"(hi)); return r;
}
__device__ __forceinline__ void upk2(float& lo, float& hi, u64 v) {
    asm("mov.b64 {%0, %1}, %2;" : "=f"(lo), "=f"(hi) : "l"(v));
}
__device__ __forceinline__ u64 mul2(u64 a, u64 b) {
    u64 r; asm("mul.rn.f32x2 %0, %1, %2;" : "=l"(r) : "l"(a), "l"(b)); return r;
}
__device__ __forceinline__ u64 fma2(u64 a, u64 b, u64 c) {
    u64 r; asm("fma.rn.f32x2 %0, %1, %2, %3;" : "=l"(r) : "l"(a), "l"(b), "l"(c)); return r;
}

__device__ __forceinline__ void load_row(const float* __restrict__ p, int r, int n, float v[16]) {
    if (r < n) {
        const float4* q = (const float4*)p + r * 4;
        #pragma unroll
        for (int i = 0; i < 4; ++i) {
            float4 t = q[i];
            v[4*i] = t.x; v[4*i+1] = t.y; v[4*i+2] = t.z; v[4*i+3] = t.w;
        }
    } else {
        #pragma unroll
        for (int i = 0; i < 16; ++i) v[i] = 0.f;
    }
}

__device__ __forceinline__ void store_row(float* __restrict__ out, int r, int n, const float v[16]) {
    if (r < n) {
        float4* q = (float4*)out + r * 4;
        #pragma unroll
        for (int i = 0; i < 4; ++i)
            q[i] = make_float4(v[4*i], v[4*i+1], v[4*i+2], v[4*i+3]);
    }
}

// ===========================================================================
// Main kernel: 4 rows/thread = two f32x2 chains; R5 loop shape duplicated
// verbatim per chain so SROA keeps everything in registers. Each cg constant
// pack (pk2) is shared by the two adjacent fma2's.
// ===========================================================================
__global__ void __launch_bounds__(128, 2)
tp_main(const float* __restrict__ x1, const float* __restrict__ x2,
        const float* __restrict__ weights, float* __restrict__ out, int n) {
    static constexpr CGT CG = make_cgt();

    const int r0 = blockIdx.x * 512 + threadIdx.x;
    const int r1 = r0 + 128, r2 = r0 + 256, r3 = r0 + 384;

    u64 X1A[16], X2A[16], X1B[16], X2B[16], ACA[16], ACB[16];
    {
        float t0[16], t1[16];
        load_row(x1, r0, n, t0); load_row(x1, r1, n, t1);
        #pragma unroll
        for (int i = 0; i < 16; ++i) X1A[i] = pk2(t0[i], t1[i]);
        load_row(x1, r2, n, t0); load_row(x1, r3, n, t1);
        #pragma unroll
        for (int i = 0; i < 16; ++i) X1B[i] = pk2(t0[i], t1[i]);
        load_row(x2, r0, n, t0); load_row(x2, r1, n, t1);
        #pragma unroll
        for (int i = 0; i < 16; ++i) X2A[i] = pk2(t0[i], t1[i]);
        load_row(x2, r2, n, t0); load_row(x2, r3, n, t1);
        #pragma unroll
        for (int i = 0; i < 16; ++i) X2B[i] = pk2(t0[i], t1[i]);
    }
    #pragma unroll
    for (int i = 0; i < 16; ++i) { ACA[i] = 0ull; ACB[i] = 0ull; }

    // Path-major contraction, R5 shape: tA/tB zero-init, straight-line pairs.
    #pragma unroll
    for (int l1 = 0; l1 <= 3; ++l1)
    #pragma unroll
    for (int l2 = 0; l2 <= 3; ++l2)
    #pragma unroll
    for (int lo = 0; lo <= 3; ++lo) {
        if ((l1 + l2 + lo) & 1) continue;
        {
            const int dl = l1 > l2 ? l1 - l2 : l2 - l1;
            if (lo < dl || lo > l1 + l2) continue;
        }
        const int p = pathof(lo, l1, l2);
        if (p < 0) continue;

        u64 tA[7], tB[7];
        #pragma unroll
        for (int i = 0; i < 7; ++i) { tA[i] = 0ull; tB[i] = 0ull; }

        #pragma unroll
        for (int m1 = -3; m1 <= 3; ++m1) {
            if (m1 < -l1 || m1 > l1) continue;
            #pragma unroll
            for (int m2 = -3; m2 <= 3; ++m2) {
                if (m2 < -l2 || m2 > l2) continue;
                const int a = l1*l1 + l1 + m1;
                const int b = l2*l2 + l2 + m2;
                const u64 paA = mul2(X1A[a], X2A[b]);  // CSE'd across lo
                const u64 paB = mul2(X1B[a], X2B[b]);
                #pragma unroll
                for (int m3 = -3; m3 <= 3; ++m3) {
                    if (m3 < -lo || m3 > lo) continue;
                    if (!term_ok(l1, m1, l2, m2, lo, m3)) continue;
                    const int c = lo*lo + lo + m3;
                    const float cg = CG.v[(a*16 + b)*16 + c]; // folds to imm
                    if (cg == 0.f) continue;
                    const u64 w = pk2(cg, cg);                // shared pack
                    const int k = lo + m3;
                    tA[k] = fma2(w, paA, tA[k]);
                    tB[k] = fma2(w, paB, tB[k]);
                }
            }
        }
        const float wp = __ldg(weights + p);
        const u64 w2 = pk2(wp, wp);
        #pragma unroll
        for (int m3 = -lo; m3 <= lo; ++m3) {
            const int c = lo*lo + lo + m3;
            const int k = lo + m3;
            ACA[c] = fma2(w2, tA[k], ACA[c]);
            ACB[c] = fma2(w2, tB[k], ACB[c]);
        }
    }

    float o0[16], o1[16], o2[16], o3[16];
    #pragma unroll
    for (int i = 0; i < 16; ++i) { upk2(o0[i], o1[i], ACA[i]); upk2(o2[i], o3[i], ACB[i]); }
    store_row(out, r0, n, o0);
    store_row(out, r1, n, o1);
    store_row(out, r2, n, o2);
    store_row(out, r3, n, o3);
}

extern "C" void kernel_launch(void* const* d_in, const int* in_sizes, int n_in,
                              void* d_out, int out_size) {
    const float* x1 = (const float*)d_in[0];
    const float* x2 = (const float*)d_in[1];
    const float* weights = (const float*)d_in[2];
    float* out = (float*)d_out;
    const int n = in_sizes[0] / 16;

    const int blocks = (n + 511) / 512;
    tp_main<<<blocks, 128>>>(x1, x2, weights, out, n);
}

// round 8
// speedup vs baseline: 14.5576x; 1.3257x over previous
#include <cuda_runtime.h>
#include <cuda_bf16.h>
#include <cstdint>

typedef unsigned long long u64;

// ===========================================================================
// Compile-time CG machinery (all constexpr, double precision)
// ===========================================================================
__host__ __device__ constexpr double cfct(int k) {
    double r = 1.0;
    for (int i = 2; i <= k; ++i) r *= (double)i;
    return r;
}
__host__ __device__ constexpr double csqrt(double x) {
    if (x <= 0.0) return 0.0;
    double g = x < 1.0 ? 1.0 : x;
    for (int i = 0; i < 40; ++i) g = 0.5 * (g + x / g);
    return g;
}
__host__ __device__ constexpr double csu2(int j1,int m1,int j2,int m2,int j3,int m3) {
    if (m1 + m2 != m3) return 0.0;
    if (m3 > j3 || m3 < -j3) return 0.0;
    int vmin = -j1 + j2 + m3; if (-j1 + m1 > vmin) vmin = -j1 + m1; if (vmin < 0) vmin = 0;
    int vmax = j2 + j3 + m1; if (j3 - j1 + j2 < vmax) vmax = j3 - j1 + j2; if (j3 + m3 < vmax) vmax = j3 + m3;
    if (vmax < vmin) return 0.0;
    double C = (2.0*j3 + 1.0)
             * (cfct(j3+j1-j2)*cfct(j3-j1+j2)*cfct(j1+j2-j3)*cfct(j3+m3)*cfct(j3-m3))
             / (cfct(j1+j2+j3+1)*cfct(j1-m1)*cfct(j1+m1)*cfct(j2-m2)*cfct(j2+m2));
    double S = 0.0;
    for (int v = vmin; v <= vmax; ++v) {
        double t = (cfct(j2+j3+m1-v)*cfct(j1-m1+v))
                 / (cfct(v)*cfct(j3-j1+j2-v)*cfct(j3+m3-v)*cfct(v+j1-j2-m3));
        S += (((v + j2 + m2) & 1) ? -t : t);
    }
    return csqrt(C) * S;
}

struct cc { double r, i; };
__host__ __device__ constexpr cc cmulc(cc a, cc b) {
    return cc{a.r*b.r - a.i*b.i, a.r*b.i + a.i*b.r};
}
__host__ __device__ constexpr cc qent(int l, int mu, int m) {
    const double invs = 0.70710678118654752440;
    cc q{0.0, 0.0};
    if (mu == 0) {
        if (m != 0) return cc{0.0, 0.0};
        q = cc{1.0, 0.0};
    } else if (mu < 0) {
        if (m == -mu)      q = cc{invs, 0.0};
        else if (m == mu)  q = cc{0.0, -invs};
        else return cc{0.0, 0.0};
    } else {
        if (m == mu)       q = cc{(mu & 1) ? -invs : invs, 0.0};
        else if (m == -mu) q = cc{0.0, (mu & 1) ? -invs : invs};
        else return cc{0.0, 0.0};
    }
    cc o{0.0, 0.0};
    switch (l & 3) {
        case 0: o = q; break;
        case 1: o = cc{ q.i, -q.r}; break;
        case 2: o = cc{-q.r, -q.i}; break;
        default: o = cc{-q.i,  q.r}; break;
    }
    return o;
}
__host__ __device__ constexpr double ccgreal(int l1,int m1,int l2,int m2,int l3,int m3) {
    double acc = 0.0;
    int am1 = m1 < 0 ? -m1 : m1;
    int am2 = m2 < 0 ? -m2 : m2;
    for (int s1 = 0; s1 < 2; ++s1) {
        if (am1 == 0 && s1 == 1) continue;
        int mu1 = s1 ? -am1 : am1;
        cc q1 = qent(l1, mu1, m1);
        for (int s2 = 0; s2 < 2; ++s2) {
            if (am2 == 0 && s2 == 1) continue;
            int mu2 = s2 ? -am2 : am2;
            int mu3 = mu1 + mu2;
            if (mu3 > l3 || mu3 < -l3) continue;
            cc q3 = qent(l3, mu3, m3);
            if (q3.r == 0.0 && q3.i == 0.0) continue;
            q3.i = -q3.i;
            double cg = csu2(l1, mu1, l2, mu2, l3, mu3);
            if (cg == 0.0) continue;
            cc t = cmulc(cmulc(q1, qent(l2, mu2, m2)), q3);
            acc += t.r * cg;
        }
    }
    return acc;
}

__host__ __device__ constexpr int pathof(int lo, int l1, int l2) {
    const signed char L[64] = {
       0,-1,-1,-1, -1, 1,-1,-1, -1,-1, 2,-1, -1,-1,-1, 3,
      -1, 4,-1,-1,  5,-1, 6,-1, -1, 7,-1, 8, -1,-1, 9,-1,
      -1,-1,10,-1, -1,11,-1,12, 13,-1,14,-1, -1,15,-1,16,
      -1,-1,-1,17, -1,-1,18,-1, -1,19,-1,20, 21,-1,22,-1
    };
    return L[lo*16 + l1*4 + l2];
}

__host__ __device__ constexpr bool term_ok(int l1,int m1,int l2,int m2,int lo,int m3) {
    if ((l1 + l2 + lo) & 1) return false;
    int dl = l1 - l2; if (dl < 0) dl = -dl;
    if (lo < dl || lo > l1 + l2) return false;
    int am1 = m1 < 0 ? -m1 : m1;
    int am2 = m2 < 0 ? -m2 : m2;
    int am3 = m3 < 0 ? -m3 : m3;
    int s = am1 + am2;
    int d = am1 - am2; if (d < 0) d = -d;
    if (am3 != s && am3 != d) return false;
    if ((((m1 < 0) ? 1 : 0) + ((m2 < 0) ? 1 : 0) + ((m3 < 0) ? 1 : 0)) & 1) return false;
    return true;
}

struct CGT { float v[4096]; };
__host__ __device__ constexpr CGT make_cgt() {
    CGT t{};
    for (int a = 0; a < 16; ++a)
    for (int b = 0; b < 16; ++b)
    for (int c = 0; c < 16; ++c) {
        int l1 = (a >= 9) ? 3 : (a >= 4) ? 2 : (a >= 1) ? 1 : 0;
        int l2 = (b >= 9) ? 3 : (b >= 4) ? 2 : (b >= 1) ? 1 : 0;
        int lo = (c >= 9) ? 3 : (c >= 4) ? 2 : (c >= 1) ? 1 : 0;
        int m1 = a - l1*l1 - l1;
        int m2 = b - l2*l2 - l2;
        int m3 = c - lo*lo - lo;
        double val = 0.0;
        if (pathof(lo, l1, l2) >= 0 && term_ok(l1, m1, l2, m2, lo, m3))
            val = csqrt(2.0*lo + 1.0) * ccgreal(l1, m1, l2, m2, lo, m3);
        t.v[(a*16 + b)*16 + c] = (float)val;
    }
    return t;
}

// ===========================================================================
// Packed f32x2 + async-copy helpers
// ===========================================================================
__device__ __forceinline__ u64 pk2(float lo, float hi) {
    u64 r; asm("mov.b64 %0, {%1, %2};" : "=l"(r) : "f"(lo), "f"(hi)); return r;
}
__device__ __forceinline__ void upk2(float& lo, float& hi, u64 v) {
    asm("mov.b64 {%0, %1}, %2;" : "=f"(lo), "=f"(hi) : "l"(v));
}
__device__ __forceinline__ u64 mul2(u64 a, u64 b) {
    u64 r; asm("mul.rn.f32x2 %0, %1, %2;" : "=l"(r) : "l"(a), "l"(b)); return r;
}
__device__ __forceinline__ u64 fma2(u64 a, u64 b, u64 c) {
    u64 r; asm("fma.rn.f32x2 %0, %1, %2, %3;" : "=l"(r) : "l"(a), "l"(b), "l"(c)); return r;
}

__device__ __forceinline__ uint32_t smem_u32(const void* p) {
    uint32_t a;
    asm("{ .reg .u64 t; cvta.to.shared.u64 t, %1; cvt.u32.u64 %0, t; }" : "=r"(a) : "l"(p));
    return a;
}
__device__ __forceinline__ void mbar_init(uint32_t mb, uint32_t cnt) {
    asm volatile("mbarrier.init.shared.b64 [%0], %1;" :: "r"(mb), "r"(cnt) : "memory");
}
__device__ __forceinline__ void mbar_expect(uint32_t mb, uint32_t bytes) {
    asm volatile("mbarrier.arrive.expect_tx.shared.b64 _, [%0], %1;" :: "r"(mb), "r"(bytes) : "memory");
}
__device__ __forceinline__ void mbar_wait(uint32_t mb, int phase) {
    asm volatile(
        "{\n\t"
        ".reg .pred P;\n\t"
        "W_%=: mbarrier.try_wait.parity.acquire.cta.shared::cta.b64 P, [%0], %1, 0x989680;\n\t"
        "@P bra D_%=;\n\t"
        "bra W_%=;\n\t"
        "D_%=:\n\t"
        "}"
        :: "r"(mb), "r"((uint32_t)phase) : "memory");
}
__device__ __forceinline__ void bulk_g2s(uint32_t dst, const void* src, uint32_t bytes, uint32_t mb) {
    asm volatile(
        "cp.async.bulk.shared::cluster.global.mbarrier::complete_tx::bytes [%0], [%1], %2, [%3];"
        :: "r"(dst), "l"(src), "r"(bytes), "r"(mb) : "memory");
}

__device__ __forceinline__ void store_row(float* __restrict__ out, int r, int n, const float v[16]) {
    if (r < n) {
        float4* q = (float4*)out + r * 4;
        #pragma unroll
        for (int i = 0; i < 4; ++i)
            q[i] = make_float4(v[4*i], v[4*i+1], v[4*i+2], v[4*i+3]);
    }
}

// ===========================================================================
// Persistent kernel: 2-stage TMA-bulk double buffer, R5 compute core.
// smem: [0,16) mbarriers, [128,+32KB) stage0 (x1|x2), [+32KB) stage1.
// ===========================================================================
#define STAGE_BYTES 32768
#define SMEM_TOTAL  (128 + 2 * STAGE_BYTES)

__global__ void __launch_bounds__(128, 3)
tp_main(const float* __restrict__ x1, const float* __restrict__ x2,
        const float* __restrict__ weights, float* __restrict__ out, int n) {
    static constexpr CGT CG = make_cgt();
    extern __shared__ __align__(16) char smem[];
    const uint32_t sbase = smem_u32(smem);
    const int tid = threadIdx.x;
    const int ntiles = (n + 255) >> 8;

    const uint32_t mb0 = sbase, mb1 = sbase + 8;
    if (tid == 0) {
        mbar_init(mb0, 1);
        mbar_init(mb1, 1);
        asm volatile("fence.proxy.async.shared::cta;" ::: "memory");
    }
    __syncthreads();

    int tile = blockIdx.x;
    if (tid == 0 && tile < ntiles) {
        const int rows = min(256, n - (tile << 8));
        const uint32_t bytes = (uint32_t)rows << 6;
        mbar_expect(mb0, bytes * 2);
        bulk_g2s(sbase + 128,          x1 + ((size_t)tile << 12), bytes, mb0);
        bulk_g2s(sbase + 128 + 16384,  x2 + ((size_t)tile << 12), bytes, mb0);
    }

    int ph0 = 0, ph1 = 0, s = 0;
    for (; tile < ntiles; tile += gridDim.x) {
        if (s == 0) { mbar_wait(mb0, ph0); ph0 ^= 1; }
        else        { mbar_wait(mb1, ph1); ph1 ^= 1; }

        // Prefetch next tile into the other stage (consumed 1 iter ago;
        // the __syncthreads() at the end of that iter makes reuse safe).
        const int nxt = tile + gridDim.x;
        if (tid == 0 && nxt < ntiles) {
            const int rows = min(256, n - (nxt << 8));
            const uint32_t bytes = (uint32_t)rows << 6;
            const uint32_t so = sbase + 128 + (uint32_t)(s ^ 1) * STAGE_BYTES;
            mbar_expect(s == 0 ? mb1 : mb0, bytes * 2);
            bulk_g2s(so,          x1 + ((size_t)nxt << 12), bytes, s == 0 ? mb1 : mb0);
            bulk_g2s(so + 16384,  x2 + ((size_t)nxt << 12), bytes, s == 0 ? mb1 : mb0);
        }

        // ---- R5 compute core, fed from shared memory ----
        const float4* s1 = (const float4*)(smem + 128 + s * STAGE_BYTES);
        const float4* s2 = (const float4*)(smem + 128 + s * STAGE_BYTES + 16384);
        const int r0 = (tile << 8) + tid;
        const int r1 = r0 + 128;

        u64 X1[16], X2[16], AC[16];
        {
            #pragma unroll
            for (int i = 0; i < 4; ++i) {
                float4 a = s1[tid * 4 + i];
                float4 b = s1[(tid + 128) * 4 + i];
                X1[4*i+0] = pk2(a.x, b.x); X1[4*i+1] = pk2(a.y, b.y);
                X1[4*i+2] = pk2(a.z, b.z); X1[4*i+3] = pk2(a.w, b.w);
            }
            #pragma unroll
            for (int i = 0; i < 4; ++i) {
                float4 a = s2[tid * 4 + i];
                float4 b = s2[(tid + 128) * 4 + i];
                X2[4*i+0] = pk2(a.x, b.x); X2[4*i+1] = pk2(a.y, b.y);
                X2[4*i+2] = pk2(a.z, b.z); X2[4*i+3] = pk2(a.w, b.w);
            }
        }
        #pragma unroll
        for (int i = 0; i < 16; ++i) AC[i] = 0ull;

        #pragma unroll
        for (int l1 = 0; l1 <= 3; ++l1)
        #pragma unroll
        for (int l2 = 0; l2 <= 3; ++l2)
        #pragma unroll
        for (int lo = 0; lo <= 3; ++lo) {
            if ((l1 + l2 + lo) & 1) continue;
            {
                const int dl = l1 > l2 ? l1 - l2 : l2 - l1;
                if (lo < dl || lo > l1 + l2) continue;
            }
            const int p = pathof(lo, l1, l2);
            if (p < 0) continue;

            u64 t[7];
            #pragma unroll
            for (int i = 0; i < 7; ++i) t[i] = 0ull;

            #pragma unroll
            for (int m1 = -3; m1 <= 3; ++m1) {
                if (m1 < -l1 || m1 > l1) continue;
                #pragma unroll
                for (int m2 = -3; m2 <= 3; ++m2) {
                    if (m2 < -l2 || m2 > l2) continue;
                    const int a = l1*l1 + l1 + m1;
                    const int b = l2*l2 + l2 + m2;
                    const u64 pa = mul2(X1[a], X2[b]);        // CSE'd across lo
                    #pragma unroll
                    for (int m3 = -3; m3 <= 3; ++m3) {
                        if (m3 < -lo || m3 > lo) continue;
                        if (!term_ok(l1, m1, l2, m2, lo, m3)) continue;
                        const int c = lo*lo + lo + m3;
                        const float cg = CG.v[(a*16 + b)*16 + c]; // imm
                        if (cg == 0.f) continue;
                        t[lo + m3] = fma2(pk2(cg, cg), pa, t[lo + m3]);
                    }
                }
            }
            const float wp = __ldg(weights + p);
            const u64 w2 = pk2(wp, wp);
            #pragma unroll
            for (int m3 = -lo; m3 <= lo; ++m3) {
                const int c = lo*lo + lo + m3;
                AC[c] = fma2(w2, t[lo + m3], AC[c]);
            }
        }

        float o0[16], o1[16];
        #pragma unroll
        for (int i = 0; i < 16; ++i) upk2(o0[i], o1[i], AC[i]);
        store_row(out, r0, n, o0);
        store_row(out, r1, n, o1);

        __syncthreads();   // all threads done reading stage s
        s ^= 1;
    }
}

extern "C" void kernel_launch(void* const* d_in, const int* in_sizes, int n_in,
                              void* d_out, int out_size) {
    const float* x1 = (const float*)d_in[0];
    const float* x2 = (const float*)d_in[1];
    const float* weights = (const float*)d_in[2];
    float* out = (float*)d_out;
    const int n = in_sizes[0] / 16;

    static int attr_done = 0;
    if (!attr_done) {
        cudaFuncSetAttribute(tp_main, cudaFuncAttributeMaxDynamicSharedMemorySize, SMEM_TOTAL);
        attr_done = 1;
    }

    const int blocks = 444;   // 3 per SM on 148 SMs; grid-stride covers all tiles
    tp_main<<<blocks, 128, SMEM_TOTAL>>>(x1, x2, weights, out, n);
}

// round 9
// speedup vs baseline: 17.4541x; 1.1990x over previous
#include <cuda_runtime.h>
#include <cuda_bf16.h>

// ===========================================================================
// Compile-time CG machinery (all constexpr, double precision)
// ===========================================================================
__host__ __device__ constexpr double cfct(int k) {
    double r = 1.0;
    for (int i = 2; i <= k; ++i) r *= (double)i;
    return r;
}
__host__ __device__ constexpr double csqrt(double x) {
    if (x <= 0.0) return 0.0;
    double g = x < 1.0 ? 1.0 : x;
    for (int i = 0; i < 40; ++i) g = 0.5 * (g + x / g);
    return g;
}
__host__ __device__ constexpr double csu2(int j1,int m1,int j2,int m2,int j3,int m3) {
    if (m1 + m2 != m3) return 0.0;
    if (m3 > j3 || m3 < -j3) return 0.0;
    int vmin = -j1 + j2 + m3; if (-j1 + m1 > vmin) vmin = -j1 + m1; if (vmin < 0) vmin = 0;
    int vmax = j2 + j3 + m1; if (j3 - j1 + j2 < vmax) vmax = j3 - j1 + j2; if (j3 + m3 < vmax) vmax = j3 + m3;
    if (vmax < vmin) return 0.0;
    double C = (2.0*j3 + 1.0)
             * (cfct(j3+j1-j2)*cfct(j3-j1+j2)*cfct(j1+j2-j3)*cfct(j3+m3)*cfct(j3-m3))
             / (cfct(j1+j2+j3+1)*cfct(j1-m1)*cfct(j1+m1)*cfct(j2-m2)*cfct(j2+m2));
    double S = 0.0;
    for (int v = vmin; v <= vmax; ++v) {
        double t = (cfct(j2+j3+m1-v)*cfct(j1-m1+v))
                 / (cfct(v)*cfct(j3-j1+j2-v)*cfct(j3+m3-v)*cfct(v+j1-j2-m3));
        S += (((v + j2 + m2) & 1) ? -t : t);
    }
    return csqrt(C) * S;
}

struct cc { double r, i; };
__host__ __device__ constexpr cc cmulc(cc a, cc b) {
    return cc{a.r*b.r - a.i*b.i, a.r*b.i + a.i*b.r};
}
__host__ __device__ constexpr cc qent(int l, int mu, int m) {
    const double invs = 0.70710678118654752440;
    cc q{0.0, 0.0};
    if (mu == 0) {
        if (m != 0) return cc{0.0, 0.0};
        q = cc{1.0, 0.0};
    } else if (mu < 0) {
        if (m == -mu)      q = cc{invs, 0.0};
        else if (m == mu)  q = cc{0.0, -invs};
        else return cc{0.0, 0.0};
    } else {
        if (m == mu)       q = cc{(mu & 1) ? -invs : invs, 0.0};
        else if (m == -mu) q = cc{0.0, (mu & 1) ? -invs : invs};
        else return cc{0.0, 0.0};
    }
    cc o{0.0, 0.0};
    switch (l & 3) {
        case 0: o = q; break;
        case 1: o = cc{ q.i, -q.r}; break;
        case 2: o = cc{-q.r, -q.i}; break;
        default: o = cc{-q.i,  q.r}; break;
    }
    return o;
}
__host__ __device__ constexpr double ccgreal(int l1,int m1,int l2,int m2,int l3,int m3) {
    double acc = 0.0;
    int am1 = m1 < 0 ? -m1 : m1;
    int am2 = m2 < 0 ? -m2 : m2;
    for (int s1 = 0; s1 < 2; ++s1) {
        if (am1 == 0 && s1 == 1) continue;
        int mu1 = s1 ? -am1 : am1;
        cc q1 = qent(l1, mu1, m1);
        for (int s2 = 0; s2 < 2; ++s2) {
            if (am2 == 0 && s2 == 1) continue;
            int mu2 = s2 ? -am2 : am2;
            int mu3 = mu1 + mu2;
            if (mu3 > l3 || mu3 < -l3) continue;
            cc q3 = qent(l3, mu3, m3);
            if (q3.r == 0.0 && q3.i == 0.0) continue;
            q3.i = -q3.i;
            double cg = csu2(l1, mu1, l2, mu2, l3, mu3);
            if (cg == 0.0) continue;
            cc t = cmulc(cmulc(q1, qent(l2, mu2, m2)), q3);
            acc += t.r * cg;
        }
    }
    return acc;
}

__host__ __device__ constexpr int pathof(int lo, int l1, int l2) {
    const signed char L[64] = {
       0,-1,-1,-1, -1, 1,-1,-1, -1,-1, 2,-1, -1,-1,-1, 3,
      -1, 4,-1,-1,  5,-1, 6,-1, -1, 7,-1, 8, -1,-1, 9,-1,
      -1,-1,10,-1, -1,11,-1,12, 13,-1,14,-1, -1,15,-1,16,
      -1,-1,-1,17, -1,-1,18,-1, -1,19,-1,20, 21,-1,22,-1
    };
    return L[lo*16 + l1*4 + l2];
}

__host__ __device__ constexpr bool term_ok(int l1,int m1,int l2,int m2,int lo,int m3) {
    if ((l1 + l2 + lo) & 1) return false;
    int dl = l1 - l2; if (dl < 0) dl = -dl;
    if (lo < dl || lo > l1 + l2) return false;
    int am1 = m1 < 0 ? -m1 : m1;
    int am2 = m2 < 0 ? -m2 : m2;
    int am3 = m3 < 0 ? -m3 : m3;
    int s = am1 + am2;
    int d = am1 - am2; if (d < 0) d = -d;
    if (am3 != s && am3 != d) return false;
    if ((((m1 < 0) ? 1 : 0) + ((m2 < 0) ? 1 : 0) + ((m3 < 0) ? 1 : 0)) & 1) return false;
    return true;
}

struct CGT { float v[4096]; };
__host__ __device__ constexpr CGT make_cgt() {
    CGT t{};
    for (int a = 0; a < 16; ++a)
    for (int b = 0; b < 16; ++b)
    for (int c = 0; c < 16; ++c) {
        int l1 = (a >= 9) ? 3 : (a >= 4) ? 2 : (a >= 1) ? 1 : 0;
        int l2 = (b >= 9) ? 3 : (b >= 4) ? 2 : (b >= 1) ? 1 : 0;
        int lo = (c >= 9) ? 3 : (c >= 4) ? 2 : (c >= 1) ? 1 : 0;
        int m1 = a - l1*l1 - l1;
        int m2 = b - l2*l2 - l2;
        int m3 = c - lo*lo - lo;
        double val = 0.0;
        if (pathof(lo, l1, l2) >= 0 && term_ok(l1, m1, l2, m2, lo, m3))
            val = csqrt(2.0*lo + 1.0) * ccgreal(l1, m1, l2, m2, lo, m3);
        t.v[(a*16 + b)*16 + c] = (float)val;
    }
    return t;
}

// ===========================================================================
// Main kernel: 1 row/thread, pure scalar fp32. Constant CG multipliers fold
// into FFMA-imm (rt_SMSP=1, no register materialization) — this removes the
// ALU MOV pressure that co-limited the packed f32x2 version, and the small
// register footprint restores occupancy.
// ===========================================================================
__global__ void __launch_bounds__(256)
tp_main(const float* __restrict__ x1, const float* __restrict__ x2,
        const float* __restrict__ weights, float* __restrict__ out, int n) {
    static constexpr CGT CG = make_cgt();

    const int r = blockIdx.x * 256 + threadIdx.x;
    if (r >= n) return;

    float X1[16], X2[16], AC[16];
    {
        const float4* q1 = (const float4*)x1 + r * 4;
        const float4* q2 = (const float4*)x2 + r * 4;
        #pragma unroll
        for (int i = 0; i < 4; ++i) {
            float4 a = q1[i];
            X1[4*i] = a.x; X1[4*i+1] = a.y; X1[4*i+2] = a.z; X1[4*i+3] = a.w;
            float4 b = q2[i];
            X2[4*i] = b.x; X2[4*i+1] = b.y; X2[4*i+2] = b.z; X2[4*i+3] = b.w;
        }
    }
    #pragma unroll
    for (int i = 0; i < 16; ++i) AC[i] = 0.f;

    // Path-major contraction: t[m3] += cg_imm * (x1[a]*x2[b]); AC += w_p * t.
    #pragma unroll
    for (int l1 = 0; l1 <= 3; ++l1)
    #pragma unroll
    for (int l2 = 0; l2 <= 3; ++l2)
    #pragma unroll
    for (int lo = 0; lo <= 3; ++lo) {
        if ((l1 + l2 + lo) & 1) continue;
        {
            const int dl = l1 > l2 ? l1 - l2 : l2 - l1;
            if (lo < dl || lo > l1 + l2) continue;
        }
        const int p = pathof(lo, l1, l2);
        if (p < 0) continue;

        float t[7];
        #pragma unroll
        for (int i = 0; i < 7; ++i) t[i] = 0.f;

        #pragma unroll
        for (int m1 = -3; m1 <= 3; ++m1) {
            if (m1 < -l1 || m1 > l1) continue;
            #pragma unroll
            for (int m2 = -3; m2 <= 3; ++m2) {
                if (m2 < -l2 || m2 > l2) continue;
                const int a = l1*l1 + l1 + m1;
                const int b = l2*l2 + l2 + m2;
                const float pa = X1[a] * X2[b];               // CSE'd across lo
                #pragma unroll
                for (int m3 = -3; m3 <= 3; ++m3) {
                    if (m3 < -lo || m3 > lo) continue;
                    if (!term_ok(l1, m1, l2, m2, lo, m3)) continue;
                    const int c = lo*lo + lo + m3;
                    const float cg = CG.v[(a*16 + b)*16 + c]; // folds to imm
                    if (cg == 0.f) continue;
                    t[lo + m3] = fmaf(cg, pa, t[lo + m3]);    // FFMA-imm
                }
            }
        }
        const float wp = __ldg(weights + p);
        #pragma unroll
        for (int m3 = -lo; m3 <= lo; ++m3) {
            const int c = lo*lo + lo + m3;
            AC[c] = fmaf(wp, t[lo + m3], AC[c]);
        }
    }

    {
        float4* q = (float4*)out + r * 4;
        #pragma unroll
        for (int i = 0; i < 4; ++i)
            q[i] = make_float4(AC[4*i], AC[4*i+1], AC[4*i+2], AC[4*i+3]);
    }
}

extern "C" void kernel_launch(void* const* d_in, const int* in_sizes, int n_in,
                              void* d_out, int out_size) {
    const float* x1 = (const float*)d_in[0];
    const float* x2 = (const float*)d_in[1];
    const float* weights = (const float*)d_in[2];
    float* out = (float*)d_out;
    const int n = in_sizes[0] / 16;

    const int blocks = (n + 255) / 256;
    tp_main<<<blocks, 256>>>(x1, x2, weights, out, n);
}

// round 10
// speedup vs baseline: 18.6317x; 1.0675x over previous
#include <cuda_runtime.h>
#include <cuda_bf16.h>

// ===========================================================================
// Compile-time CG machinery (all constexpr, double precision)
// ===========================================================================
__host__ __device__ constexpr double cfct(int k) {
    double r = 1.0;
    for (int i = 2; i <= k; ++i) r *= (double)i;
    return r;
}
__host__ __device__ constexpr double csqrt(double x) {
    if (x <= 0.0) return 0.0;
    double g = x < 1.0 ? 1.0 : x;
    for (int i = 0; i < 40; ++i) g = 0.5 * (g + x / g);
    return g;
}
__host__ __device__ constexpr double csu2(int j1,int m1,int j2,int m2,int j3,int m3) {
    if (m1 + m2 != m3) return 0.0;
    if (m3 > j3 || m3 < -j3) return 0.0;
    int vmin = -j1 + j2 + m3; if (-j1 + m1 > vmin) vmin = -j1 + m1; if (vmin < 0) vmin = 0;
    int vmax = j2 + j3 + m1; if (j3 - j1 + j2 < vmax) vmax = j3 - j1 + j2; if (j3 + m3 < vmax) vmax = j3 + m3;
    if (vmax < vmin) return 0.0;
    double C = (2.0*j3 + 1.0)
             * (cfct(j3+j1-j2)*cfct(j3-j1+j2)*cfct(j1+j2-j3)*cfct(j3+m3)*cfct(j3-m3))
             / (cfct(j1+j2+j3+1)*cfct(j1-m1)*cfct(j1+m1)*cfct(j2-m2)*cfct(j2+m2));
    double S = 0.0;
    for (int v = vmin; v <= vmax; ++v) {
        double t = (cfct(j2+j3+m1-v)*cfct(j1-m1+v))
                 / (cfct(v)*cfct(j3-j1+j2-v)*cfct(j3+m3-v)*cfct(v+j1-j2-m3));
        S += (((v + j2 + m2) & 1) ? -t : t);
    }
    return csqrt(C) * S;
}

struct cc { double r, i; };
__host__ __device__ constexpr cc cmulc(cc a, cc b) {
    return cc{a.r*b.r - a.i*b.i, a.r*b.i + a.i*b.r};
}
__host__ __device__ constexpr cc qent(int l, int mu, int m) {
    const double invs = 0.70710678118654752440;
    cc q{0.0, 0.0};
    if (mu == 0) {
        if (m != 0) return cc{0.0, 0.0};
        q = cc{1.0, 0.0};
    } else if (mu < 0) {
        if (m == -mu)      q = cc{invs, 0.0};
        else if (m == mu)  q = cc{0.0, -invs};
        else return cc{0.0, 0.0};
    } else {
        if (m == mu)       q = cc{(mu & 1) ? -invs : invs, 0.0};
        else if (m == -mu) q = cc{0.0, (mu & 1) ? -invs : invs};
        else return cc{0.0, 0.0};
    }
    cc o{0.0, 0.0};
    switch (l & 3) {
        case 0: o = q; break;
        case 1: o = cc{ q.i, -q.r}; break;
        case 2: o = cc{-q.r, -q.i}; break;
        default: o = cc{-q.i,  q.r}; break;
    }
    return o;
}
__host__ __device__ constexpr double ccgreal(int l1,int m1,int l2,int m2,int l3,int m3) {
    double acc = 0.0;
    int am1 = m1 < 0 ? -m1 : m1;
    int am2 = m2 < 0 ? -m2 : m2;
    for (int s1 = 0; s1 < 2; ++s1) {
        if (am1 == 0 && s1 == 1) continue;
        int mu1 = s1 ? -am1 : am1;
        cc q1 = qent(l1, mu1, m1);
        for (int s2 = 0; s2 < 2; ++s2) {
            if (am2 == 0 && s2 == 1) continue;
            int mu2 = s2 ? -am2 : am2;
            int mu3 = mu1 + mu2;
            if (mu3 > l3 || mu3 < -l3) continue;
            cc q3 = qent(l3, mu3, m3);
            if (q3.r == 0.0 && q3.i == 0.0) continue;
            q3.i = -q3.i;
            double cg = csu2(l1, mu1, l2, mu2, l3, mu3);
            if (cg == 0.0) continue;
            cc t = cmulc(cmulc(q1, qent(l2, mu2, m2)), q3);
            acc += t.r * cg;
        }
    }
    return acc;
}

__host__ __device__ constexpr int pathof(int lo, int l1, int l2) {
    const signed char L[64] = {
       0,-1,-1,-1, -1, 1,-1,-1, -1,-1, 2,-1, -1,-1,-1, 3,
      -1, 4,-1,-1,  5,-1, 6,-1, -1, 7,-1, 8, -1,-1, 9,-1,
      -1,-1,10,-1, -1,11,-1,12, 13,-1,14,-1, -1,15,-1,16,
      -1,-1,-1,17, -1,-1,18,-1, -1,19,-1,20, 21,-1,22,-1
    };
    return L[lo*16 + l1*4 + l2];
}

__host__ __device__ constexpr bool term_ok(int l1,int m1,int l2,int m2,int lo,int m3) {
    if ((l1 + l2 + lo) & 1) return false;
    int dl = l1 - l2; if (dl < 0) dl = -dl;
    if (lo < dl || lo > l1 + l2) return false;
    int am1 = m1 < 0 ? -m1 : m1;
    int am2 = m2 < 0 ? -m2 : m2;
    int am3 = m3 < 0 ? -m3 : m3;
    int s = am1 + am2;
    int d = am1 - am2; if (d < 0) d = -d;
    if (am3 != s && am3 != d) return false;
    if ((((m1 < 0) ? 1 : 0) + ((m2 < 0) ? 1 : 0) + ((m3 < 0) ? 1 : 0)) & 1) return false;
    return true;
}

struct CGT { float v[4096]; };
__host__ __device__ constexpr CGT make_cgt() {
    CGT t{};
    for (int a = 0; a < 16; ++a)
    for (int b = 0; b < 16; ++b)
    for (int c = 0; c < 16; ++c) {
        int l1 = (a >= 9) ? 3 : (a >= 4) ? 2 : (a >= 1) ? 1 : 0;
        int l2 = (b >= 9) ? 3 : (b >= 4) ? 2 : (b >= 1) ? 1 : 0;
        int lo = (c >= 9) ? 3 : (c >= 4) ? 2 : (c >= 1) ? 1 : 0;
        int m1 = a - l1*l1 - l1;
        int m2 = b - l2*l2 - l2;
        int m3 = c - lo*lo - lo;
        double val = 0.0;
        if (pathof(lo, l1, l2) >= 0 && term_ok(l1, m1, l2, m2, lo, m3))
            val = csqrt(2.0*lo + 1.0) * ccgreal(l1, m1, l2, m2, lo, m3);
        t.v[(a*16 + b)*16 + c] = (float)val;
    }
    return t;
}

// ===========================================================================
// Main kernel: scalar fp32, FFMA-imm CG constants (R9 core), persistent
// grid-stride so every warp stays resident — no wave transitions, no CTA
// churn; steady-state LDG stream keeps the DRAM queue full.
// ===========================================================================
__global__ void __launch_bounds__(256)
tp_main(const float* __restrict__ x1, const float* __restrict__ x2,
        const float* __restrict__ weights, float* __restrict__ out, int n) {
    static constexpr CGT CG = make_cgt();

    const int stride = gridDim.x * 256;
    for (int r = blockIdx.x * 256 + threadIdx.x; r < n; r += stride) {

        float X1[16], X2[16], AC[16];
        {
            const float4* q1 = (const float4*)x1 + r * 4;
            const float4* q2 = (const float4*)x2 + r * 4;
            #pragma unroll
            for (int i = 0; i < 4; ++i) {
                float4 a = q1[i];
                X1[4*i] = a.x; X1[4*i+1] = a.y; X1[4*i+2] = a.z; X1[4*i+3] = a.w;
                float4 b = q2[i];
                X2[4*i] = b.x; X2[4*i+1] = b.y; X2[4*i+2] = b.z; X2[4*i+3] = b.w;
            }
        }
        #pragma unroll
        for (int i = 0; i < 16; ++i) AC[i] = 0.f;

        // Path-major: t[m3] += cg_imm * (x1[a]*x2[b]); AC += w_p * t.
        #pragma unroll
        for (int l1 = 0; l1 <= 3; ++l1)
        #pragma unroll
        for (int l2 = 0; l2 <= 3; ++l2)
        #pragma unroll
        for (int lo = 0; lo <= 3; ++lo) {
            if ((l1 + l2 + lo) & 1) continue;
            {
                const int dl = l1 > l2 ? l1 - l2 : l2 - l1;
                if (lo < dl || lo > l1 + l2) continue;
            }
            const int p = pathof(lo, l1, l2);
            if (p < 0) continue;

            float t[7];
            #pragma unroll
            for (int i = 0; i < 7; ++i) t[i] = 0.f;

            #pragma unroll
            for (int m1 = -3; m1 <= 3; ++m1) {
                if (m1 < -l1 || m1 > l1) continue;
                #pragma unroll
                for (int m2 = -3; m2 <= 3; ++m2) {
                    if (m2 < -l2 || m2 > l2) continue;
                    const int a = l1*l1 + l1 + m1;
                    const int b = l2*l2 + l2 + m2;
                    const float pa = X1[a] * X2[b];               // CSE'd across lo
                    #pragma unroll
                    for (int m3 = -3; m3 <= 3; ++m3) {
                        if (m3 < -lo || m3 > lo) continue;
                        if (!term_ok(l1, m1, l2, m2, lo, m3)) continue;
                        const int c = lo*lo + lo + m3;
                        const float cg = CG.v[(a*16 + b)*16 + c]; // folds to imm
                        if (cg == 0.f) continue;
                        t[lo + m3] = fmaf(cg, pa, t[lo + m3]);    // FFMA-imm
                    }
                }
            }
            const float wp = __ldg(weights + p);
            #pragma unroll
            for (int m3 = -lo; m3 <= lo; ++m3) {
                const int c = lo*lo + lo + m3;
                AC[c] = fmaf(wp, t[lo + m3], AC[c]);
            }
        }

        {
            float4* q = (float4*)out + r * 4;
            #pragma unroll
            for (int i = 0; i < 4; ++i)
                q[i] = make_float4(AC[4*i], AC[4*i+1], AC[4*i+2], AC[4*i+3]);
        }
    }
}

extern "C" void kernel_launch(void* const* d_in, const int* in_sizes, int n_in,
                              void* d_out, int out_size) {
    const float* x1 = (const float*)d_in[0];
    const float* x2 = (const float*)d_in[1];
    const float* weights = (const float*)d_in[2];
    float* out = (float*)d_out;
    const int n = in_sizes[0] / 16;

    // Persistent sizing: exactly fill the chip (host-side queries only;
    // graph-capture safe, no allocation).
    int dev = 0, nsm = 148, perSm = 0;
    cudaGetDevice(&dev);
    cudaDeviceGetAttribute(&nsm, cudaDevAttrMultiProcessorCount, dev);
    cudaOccupancyMaxActiveBlocksPerMultiprocessor(&perSm, tp_main, 256, 0);
    if (perSm < 1) perSm = 1;

    int blocks = nsm * perSm;
    const int work_blocks = (n + 255) / 256;
    if (blocks > work_blocks) blocks = work_blocks;

    tp_main<<<blocks, 256>>>(x1, x2, weights, out, n);
}